// round 16
// baseline (speedup 1.0000x reference)
#include <cuda_runtime.h>
#include <cuda_bf16.h>
#include <cstdint>

// ---------------------------------------------------------------------------
// PointNet Set Abstraction — round 16 (= round 15 + f32x2 A-stage in mid64).
// fps+prep(1) -> ballquery+xstat(2) -> mid64(3, persistent, ldmatrix)
// -> mid128(4, persistent, ldmatrix, reg epilogue) -> finalize(5).
// ---------------------------------------------------------------------------

#define BB    16
#define NN    4096
#define SS    1024
#define NSAMP 32
#define ROWS  (BB*SS*NSAMP)      // 524288
#define BN_EPS 1e-5f
#define NTILE 4096
#define GRID_MID 444             // 3 blocks/SM x 148 SMs

// ------------------------- scratch (device globals) ------------------------
__device__ float g_Xt[9*ROWS];              // gathered features [k][row]
__device__ float g_H1[(size_t)ROWS*64];     // pre-BN layer1 output
__device__ float g_M2[BB*SS*128];           // per-group max of pre-BN layer2

__device__ __align__(16) __nv_bfloat16 g_W1h[64*64],  g_W1m[64*64];
__device__ __align__(16) __nv_bfloat16 g_W2h[128*64], g_W2m[128*64];

__device__ float g_XS[54];                  // [0..8]=Σx, [9..53]=Σxxᵀ (upper)
__device__ float g_sum1[64], g_sq1[64];
__device__ float g_sum2[128], g_sq2[128];

// ----------------------------- mma helpers ---------------------------------
__device__ __forceinline__ void mma_bf16(float* acc, const uint32_t* a,
                                         uint32_t b0, uint32_t b1) {
    asm volatile(
        "mma.sync.aligned.m16n8k16.row.col.f32.bf16.bf16.f32 "
        "{%0,%1,%2,%3}, {%4,%5,%6,%7}, {%8,%9}, {%0,%1,%2,%3};"
        : "+f"(acc[0]), "+f"(acc[1]), "+f"(acc[2]), "+f"(acc[3])
        : "r"(a[0]), "r"(a[1]), "r"(a[2]), "r"(a[3]), "r"(b0), "r"(b1));
}
__device__ __forceinline__ uint32_t pk2(float lo, float hi) {
    uint32_t r;
    asm("cvt.rn.bf16x2.f32 %0, %1, %2;" : "=r"(r) : "f"(hi), "f"(lo));
    return r;
}
__device__ __forceinline__ unsigned long long pk4(float v0, float v1,
                                                  float v2, float v3) {
    unsigned long long r;
    uint32_t lo = pk2(v0, v1), hi = pk2(v2, v3);
    asm("mov.b64 %0, {%1, %2};" : "=l"(r) : "r"(lo), "r"(hi));
    return r;
}
__device__ __forceinline__ float bf16_res(float v) {
    return v - __bfloat162float(__float2bfloat16(v));
}
__device__ __forceinline__ uint32_t s2u(const void* p) {
    return (uint32_t)__cvta_generic_to_shared(p);
}
__device__ __forceinline__ void ldsm4(uint32_t* r, uint32_t a) {
    asm volatile("ldmatrix.sync.aligned.m8n8.x4.shared.b16 {%0,%1,%2,%3}, [%4];"
        : "=r"(r[0]), "=r"(r[1]), "=r"(r[2]), "=r"(r[3]) : "r"(a));
}

// --------------------------- f32x2 helpers ----------------------------------
__device__ __forceinline__ unsigned long long pack2(float lo, float hi) {
    unsigned long long r; asm("mov.b64 %0, {%1, %2};" : "=l"(r) : "f"(lo), "f"(hi)); return r;
}
__device__ __forceinline__ unsigned long long splat2(float x) {
    unsigned long long r; asm("mov.b64 %0, {%1, %1};" : "=l"(r) : "f"(x)); return r;
}
__device__ __forceinline__ float2 unpack2(unsigned long long v) {
    float lo, hi; asm("mov.b64 {%0, %1}, %2;" : "=f"(lo), "=f"(hi) : "l"(v));
    return make_float2(lo, hi);
}
__device__ __forceinline__ unsigned long long add2(unsigned long long a, unsigned long long b) {
    unsigned long long r; asm("add.rn.f32x2 %0, %1, %2;" : "=l"(r) : "l"(a), "l"(b)); return r;
}
__device__ __forceinline__ unsigned long long mul2(unsigned long long a, unsigned long long b) {
    unsigned long long r; asm("mul.rn.f32x2 %0, %1, %2;" : "=l"(r) : "l"(a), "l"(b)); return r;
}
__device__ __forceinline__ unsigned long long fma2p(unsigned long long a, unsigned long long b,
                                                    unsigned long long c) {
    unsigned long long r; asm("fma.rn.f32x2 %0, %1, %2, %3;" : "=l"(r) : "l"(a), "l"(b), "l"(c)); return r;
}

// ------------------------- FPS (blocks 0-15) + prep (16-40) -----------------
__global__ __launch_bounds__(512) void fps_prep_kernel(
    const float* __restrict__ xyz, float* __restrict__ new_xyz,
    const float* __restrict__ W1, const float* __restrict__ W2)
{
    const int bid = blockIdx.x;
    const int t = threadIdx.x;

    if (bid >= 16) {                       // ---- prep roles ----
        if (bid < 24) {
            int i = (bid-16)*512 + t;
            float v = W1[i];
            __nv_bfloat16 h = __float2bfloat16(v);
            g_W1h[i] = h;
            g_W1m[i] = __float2bfloat16(v - __bfloat162float(h));
        } else if (bid < 40) {
            int i = (bid-24)*512 + t;
            float v = W2[i];
            __nv_bfloat16 h = __float2bfloat16(v);
            g_W2h[i] = h;
            g_W2m[i] = __float2bfloat16(v - __bfloat162float(h));
        } else {
            if (t < 54)  g_XS[t] = 0.f;
            if (t < 64)  { g_sum1[t] = 0.f; g_sq1[t] = 0.f; }
            if (t < 128) { g_sum2[t] = 0.f; g_sq2[t] = 0.f; }
        }
        return;
    }

    // ---- FPS ----
    extern __shared__ float fsm[];
    float* sxyz = fsm;                     // NN*3
    float* swd  = fsm + NN*3;              // 2*32
    int*   swi  = (int*)(swd + 64);        // 2*32

    const int b = bid;
    const int lane = t & 31, wid = t >> 5;
    const float* Xp = xyz + (long)b*NN*3;

    float lx[8], ly[8], lz[8], dist[8];
#pragma unroll
    for (int i = 0; i < 8; i++) {
        int j = t + i*512;
        float x = Xp[j*3+0], y = Xp[j*3+1], z = Xp[j*3+2];
        lx[i] = x; ly[i] = y; lz[i] = z; dist[i] = 1e10f;
        sxyz[j*3+0] = x; sxyz[j*3+1] = y; sxyz[j*3+2] = z;
    }
    unsigned long long pX[4], pY[4], pZ[4];
#pragma unroll
    for (int j = 0; j < 4; j++) {
        pX[j] = pack2(lx[2*j], lx[2*j+1]);
        pY[j] = pack2(ly[2*j], ly[2*j+1]);
        pZ[j] = pack2(lz[2*j], lz[2*j+1]);
    }
    if (t < 64) { swd[t] = 0.f; swi[t] = 0x7FFFFFFF; }
    __syncthreads();

    int win = 0;
    for (int s = 0; s < SS; s++) {
        const float cx = sxyz[win*3+0], cy = sxyz[win*3+1], cz = sxyz[win*3+2];
        if (t == 0) {
            float* o = new_xyz + ((long)b*SS + s)*3;
            o[0] = cx; o[1] = cy; o[2] = cz;
        }
        const unsigned long long ax = splat2(-cx), ay = splat2(-cy), az = splat2(-cz);
        float bd = -1.0f; int bi = 0;
#pragma unroll
        for (int j = 0; j < 4; j++) {
            unsigned long long dx = add2(pX[j], ax);
            unsigned long long dy = add2(pY[j], ay);
            unsigned long long dz = add2(pZ[j], az);
            unsigned long long dd = mul2(dx, dx);
            dd = fma2p(dy, dy, dd);
            dd = fma2p(dz, dz, dd);
            float2 d = unpack2(dd);
            float dm0 = fminf(dist[2*j],   d.x); dist[2*j]   = dm0;
            if (dm0 > bd) { bd = dm0; bi = t + (2*j)*512; }
            float dm1 = fminf(dist[2*j+1], d.y); dist[2*j+1] = dm1;
            if (dm1 > bd) { bd = dm1; bi = t + (2*j+1)*512; }
        }
        unsigned ud   = __float_as_uint(bd);
        unsigned m    = __reduce_max_sync(0xFFFFFFFFu, ud);
        unsigned cand = (ud == m) ? (unsigned)bi : 0xFFFFFFFFu;
        unsigned wmin = __reduce_min_sync(0xFFFFFFFFu, cand);
        const int p = s & 1;
        if (lane == 0) { swd[p*32+wid] = __uint_as_float(m); swi[p*32+wid] = (int)wmin; }
        __syncthreads();
        float vd = swd[p*32+lane]; int vi = swi[p*32+lane];
        unsigned ud2 = __float_as_uint(vd);
        unsigned m2  = __reduce_max_sync(0xFFFFFFFFu, ud2);
        unsigned c2  = (ud2 == m2) ? (unsigned)vi : 0xFFFFFFFFu;
        win = (int)__reduce_min_sync(0xFFFFFFFFu, c2);
    }
}

// ------------------- ball query + gather + xstat (fused) --------------------
__global__ __launch_bounds__(256) void ballquery_kernel(
    const float* __restrict__ xyz, const float* __restrict__ points,
    const float* __restrict__ new_xyz)
{
    __shared__ int   sidx[8][NSAMP];
    __shared__ float red[8][54];
    const int warp = threadIdx.x >> 5, lane = threadIdx.x & 31;
    const int g = blockIdx.x*8 + warp;
    const int b = g >> 10;
    const float* Xp = xyz + (long)b*NN*3;

    const float cx = new_xyz[g*3+0], cy = new_xyz[g*3+1], cz = new_xyz[g*3+2];
    const float sa = cx*cx + cy*cy + cz*cz;
    const float R2 = (float)(0.2*0.2);
    const unsigned pm = (1u << lane) - 1u;

    int cnt = 0;
    float x0 = Xp[lane*3+0],      y0 = Xp[lane*3+1],      z0 = Xp[lane*3+2];
    float x1 = Xp[(lane+32)*3+0], y1 = Xp[(lane+32)*3+1], z1 = Xp[(lane+32)*3+2];

    for (int base = 0; base < NN && cnt < NSAMP; base += 64) {
        const int nb = (base + 64 < NN) ? base + 64 : base;
        float nx0 = Xp[(nb+lane)*3+0],    ny0 = Xp[(nb+lane)*3+1],    nz0 = Xp[(nb+lane)*3+2];
        float nx1 = Xp[(nb+lane+32)*3+0], ny1 = Xp[(nb+lane+32)*3+1], nz1 = Xp[(nb+lane+32)*3+2];

        float sb0  = x0*x0 + y0*y0 + z0*z0;
        float dot0 = cx*x0 + cy*y0 + cz*z0;
        float sqr0 = (sa - 2.0f*dot0) + sb0;
        float sb1  = x1*x1 + y1*y1 + z1*z1;
        float dot1 = cx*x1 + cy*y1 + cz*z1;
        float sqr1 = (sa - 2.0f*dot1) + sb1;

        bool v0 = !(sqr0 > R2), v1 = !(sqr1 > R2);
        unsigned m0 = __ballot_sync(0xFFFFFFFFu, v0);
        unsigned m1 = __ballot_sync(0xFFFFFFFFu, v1);
        int pos0 = cnt + __popc(m0 & pm);
        if (v0 && pos0 < NSAMP) sidx[warp][pos0] = base + lane;
        int c0 = cnt + __popc(m0);
        int pos1 = c0 + __popc(m1 & pm);
        if (v1 && pos1 < NSAMP) sidx[warp][pos1] = base + 32 + lane;
        cnt = c0 + __popc(m1);

        x0 = nx0; y0 = ny0; z0 = nz0;
        x1 = nx1; y1 = ny1; z1 = nz1;
    }
    __syncwarp();
    int c = cnt < NSAMP ? cnt : NSAMP;
    int j = sidx[warp][lane < c ? lane : 0];

    const int row = g*NSAMP + lane;
    float xv[9];
    xv[0] = Xp[j*3+0] - cx;
    xv[1] = Xp[j*3+1] - cy;
    xv[2] = Xp[j*3+2] - cz;
    const float* pp = points + ((long)b*NN + j)*6;
#pragma unroll
    for (int q = 0; q < 6; q++) xv[3+q] = pp[q];
#pragma unroll
    for (int k = 0; k < 9; k++) g_Xt[(long)k*ROWS + row] = xv[k];

    float p54[54];
#pragma unroll
    for (int i = 0; i < 9; i++) p54[i] = xv[i];
    {
        int idx = 9;
#pragma unroll
        for (int i = 0; i < 9; i++)
#pragma unroll
            for (int jj = i; jj < 9; jj++) p54[idx++] = xv[i]*xv[jj];
    }
#pragma unroll
    for (int k = 0; k < 54; k++) {
#pragma unroll
        for (int o = 16; o; o >>= 1)
            p54[k] += __shfl_xor_sync(0xFFFFFFFFu, p54[k], o);
    }
    if (lane == 0) {
#pragma unroll
        for (int k = 0; k < 54; k++) red[warp][k] = p54[k];
    }
    __syncthreads();
    if (threadIdx.x < 54) {
        float v = 0.f;
#pragma unroll
        for (int w = 0; w < 8; w++) v += red[w][threadIdx.x];
        atomicAdd(&g_XS[threadIdx.x], v);
    }
}

// --------------------------- smem layouts ------------------------------------
#define CTL_SC   4
#define CTL_SH   68
#define CTL_BS   132
#define CTL_PS   260
#define CTL_PQ   516
#define CTL_W0   772
#define CTL_B0   1348
#define STG      8192
#define M128_PS  260
#define M128_PQ  388
#define STG128   2304
#define SA       72          // padded row stride in bf16 (144 B, 16B-aligned)

// ------------------------------ mid64 (mma) ---------------------------------
// Persistent; 32x32 warp tiles, ldmatrix, tile epilogue; f32x2 A-stage.
__global__ __launch_bounds__(256, 3) void mid64_mma_kernel(
    const float* __restrict__ W0, const float* __restrict__ b0,
    const float* __restrict__ g0, const float* __restrict__ bb0,
    const float* __restrict__ b1)
{
    extern __shared__ __align__(16) char sm[];
    float* f = (float*)sm;
    const int t = threadIdx.x;
    const int w = t >> 5, lane = t & 31;

    __nv_bfloat16* Ah = (__nv_bfloat16*)(sm + STG);
    __nv_bfloat16* Am = (__nv_bfloat16*)(sm + STG + 18432);
    __nv_bfloat16* Bh = (__nv_bfloat16*)(sm + STG + 36864);
    __nv_bfloat16* Bm = (__nv_bfloat16*)(sm + STG + 46080);
    float* tile = (float*)(sm + STG);

    // ---- prologue (once per block) ----
    if (t < 64) {
        float wv[9];
#pragma unroll
        for (int k = 0; k < 9; k++) wv[k] = W0[t*9 + k];
        float sdot = 0.f;
#pragma unroll
        for (int k = 0; k < 9; k++) sdot += wv[k]*g_XS[k];
        float quad = 0.f;
        int idx = 9;
#pragma unroll
        for (int i = 0; i < 9; i++)
#pragma unroll
            for (int jj = i; jj < 9; jj++) {
                float m = g_XS[idx++];
                quad += ((i == jj) ? wv[i]*wv[i] : 2.f*wv[i]*wv[jj]) * m;
            }
        const float N = (float)ROWS;
        float bc  = b0[t];
        float mu  = (sdot + N*bc) / N;
        float Eh2 = (quad + 2.f*bc*sdot + N*bc*bc) / N;
        float var = Eh2 - mu*mu;
        if (var < 0.f) var = 0.f;
        float s = g0[t] * rsqrtf(var + BN_EPS);
        f[CTL_SC + t] = s;
        f[CTL_SH + t] = bb0[t] - mu*s;
        f[CTL_BS + t] = b1[t];
        f[CTL_B0 + t] = b0[t];
    }
    for (int i = t; i < 576; i += 256) {
        int cc = i/9, k = i - cc*9;
        f[CTL_W0 + k*64 + cc] = W0[i];
    }
    {
        const uint32_t* wh = (const uint32_t*)g_W1h;
        const uint32_t* wm = (const uint32_t*)g_W1m;
        for (int i = t; i < 2048; i += 256) {
            int n = i >> 5, kk = i & 31;
            *(uint32_t*)&Bh[n*SA + kk*2] = wh[i];
            *(uint32_t*)&Bm[n*SA + kk*2] = wm[i];
        }
    }
    __syncthreads();

    const int mg = w >> 1, ng = w & 1;
    const int m0 = mg*32, nb = ng*32;
    const int fr = lane >> 2, c2 = (lane & 3)*2;
    const int arow = lane & 15;
    const uint32_t acolB = (uint32_t)(lane >> 4) * 16u;
    const uint32_t aHa = s2u(Ah + (m0 + arow)*SA) + acolB;
    const uint32_t aMa = s2u(Am + (m0 + arow)*SA) + acolB;
    const int brow = ((lane >> 4) << 3) + (lane & 7);
    const uint32_t bcolB = (uint32_t)((lane >> 3) & 1) * 16u;
    uint32_t bHa[2], bMa[2];
#pragma unroll
    for (int pg = 0; pg < 2; pg++) {
        bHa[pg] = s2u(Bh + (nb + pg*16 + brow)*SA) + bcolB;
        bMa[pg] = s2u(Bm + (nb + pg*16 + brow)*SA) + bcolB;
    }
    const int scc = t & 63, sq4 = t >> 6;   // stats role
    float accS = 0.f, accQ = 0.f;

    // ---- tile loop ----
    for (int ti = blockIdx.x; ti < NTILE; ti += GRID_MID) {
        const long row0 = (long)ti * 128;

        // stage A: recompute H0 row r (f32x2); bn0+relu; split (64-bit stores)
        {
            const int r  = t & 127;
            const int cb = (t >> 7) * 32;
            float x[9];
#pragma unroll
            for (int k = 0; k < 9; k++) x[k] = g_Xt[(long)k*ROWS + row0 + r];
            unsigned long long acc2[16];
            {
                const unsigned long long* bp =
                    (const unsigned long long*)(f + CTL_B0 + cb);
#pragma unroll
                for (int c = 0; c < 16; c++) acc2[c] = bp[c];
            }
#pragma unroll
            for (int k = 0; k < 9; k++) {
                unsigned long long xk = splat2(x[k]);
                const unsigned long long* wr =
                    (const unsigned long long*)(f + CTL_W0 + k*64 + cb);
#pragma unroll
                for (int c = 0; c < 16; c++) acc2[c] = fma2p(xk, wr[c], acc2[c]);
            }
            // bn scale+shift packed, relu scalar
            const unsigned long long* scp =
                (const unsigned long long*)(f + CTL_SC + cb);
            const unsigned long long* shp =
                (const unsigned long long*)(f + CTL_SH + cb);
            float av[32];
#pragma unroll
            for (int c = 0; c < 16; c++) {
                unsigned long long r2 = fma2p(acc2[c], scp[c], shp[c]);
                float2 p = unpack2(r2);
                av[2*c]   = fmaxf(p.x, 0.f);
                av[2*c+1] = fmaxf(p.y, 0.f);
            }
#pragma unroll
            for (int j2 = 0; j2 < 8; j2++) {
                float v0 = av[4*j2], v1 = av[4*j2+1];
                float v2 = av[4*j2+2], v3 = av[4*j2+3];
                *(unsigned long long*)&Ah[r*SA + cb + 4*j2] = pk4(v0, v1, v2, v3);
                *(unsigned long long*)&Am[r*SA + cb + 4*j2] =
                    pk4(bf16_res(v0), bf16_res(v1), bf16_res(v2), bf16_res(v3));
            }
        }
        __syncthreads();

        float acc[2][4][4];
#pragma unroll
        for (int mt = 0; mt < 2; mt++)
#pragma unroll
            for (int nt = 0; nt < 4; nt++)
#pragma unroll
                for (int q = 0; q < 4; q++) acc[mt][nt][q] = 0.f;

#pragma unroll
        for (int ks = 0; ks < 4; ks++) {
            uint32_t aH0[4], aH1[4], aM0[4], aM1[4];
            ldsm4(aH0, aHa + ks*32);
            ldsm4(aH1, aHa + 2304 + ks*32);
            ldsm4(aM0, aMa + ks*32);
            ldsm4(aM1, aMa + 2304 + ks*32);
#pragma unroll
            for (int pg = 0; pg < 2; pg++) {
                uint32_t bH[4], bM[4];
                ldsm4(bH, bHa[pg] + ks*32);
                ldsm4(bM, bMa[pg] + ks*32);
#pragma unroll
                for (int sub = 0; sub < 2; sub++) {
                    const int nt = 2*pg + sub;
                    mma_bf16(acc[0][nt], aH0, bH[2*sub], bH[2*sub+1]);
                    mma_bf16(acc[0][nt], aH0, bM[2*sub], bM[2*sub+1]);
                    mma_bf16(acc[0][nt], aM0, bH[2*sub], bH[2*sub+1]);
                    mma_bf16(acc[1][nt], aH1, bH[2*sub], bH[2*sub+1]);
                    mma_bf16(acc[1][nt], aH1, bM[2*sub], bM[2*sub+1]);
                    mma_bf16(acc[1][nt], aM1, bH[2*sub], bH[2*sub+1]);
                }
            }
        }
        __syncthreads();   // A smem done; tile aliases it

#pragma unroll
        for (int mt = 0; mt < 2; mt++)
#pragma unroll
            for (int nt = 0; nt < 4; nt++) {
                const int col = nb + nt*8 + c2;
                float bA = f[CTL_BS + col], bB = f[CTL_BS + col + 1];
                *(float2*)&tile[(m0+mt*16+fr)*68 + col] =
                    make_float2(acc[mt][nt][0]+bA, acc[mt][nt][1]+bB);
                *(float2*)&tile[(m0+mt*16+fr+8)*68 + col] =
                    make_float2(acc[mt][nt][2]+bA, acc[mt][nt][3]+bB);
            }
        __syncthreads();

        {
            float s = 0.f, sq = 0.f;
#pragma unroll
            for (int i = 0; i < 32; i++) {
                float v = tile[(32*sq4 + i)*68 + scc];
                s += v; sq += v*v;
            }
            accS += s; accQ += sq;
        }
        for (int idx = t; idx < 2048; idx += 256) {
            int r = idx >> 4, c4 = idx & 15;
            float4 v = *(const float4*)(tile + r*68 + c4*4);
            *(float4*)(g_H1 + (size_t)(row0 + r)*64 + c4*4) = v;
        }
        __syncthreads();   // tile reads done before next A stage
    }

    // ---- final stats flush ----
    f[CTL_PS + sq4*64 + scc] = accS;
    f[CTL_PQ + sq4*64 + scc] = accQ;
    __syncthreads();
    if (t < 64) {
        float s  = f[CTL_PS+t] + f[CTL_PS+64+t] + f[CTL_PS+128+t] + f[CTL_PS+192+t];
        float sq = f[CTL_PQ+t] + f[CTL_PQ+64+t] + f[CTL_PQ+128+t] + f[CTL_PQ+192+t];
        atomicAdd(&g_sum1[t], s);
        atomicAdd(&g_sq1[t],  sq);
    }
}

// ------------------------------ mid128 (mma) --------------------------------
// Persistent; two 32-col passes, ldmatrix, register epilogue; 64-bit A-staging.
__global__ __launch_bounds__(256, 3) void mid128_mma_kernel(
    const float* __restrict__ g1, const float* __restrict__ bb1,
    const float* __restrict__ b2)
{
    extern __shared__ __align__(16) char sm[];
    float* f = (float*)sm;
    const int t = threadIdx.x;
    const int w = t >> 5, lane = t & 31;

    __nv_bfloat16* Ah = (__nv_bfloat16*)(sm + STG128);
    __nv_bfloat16* Am = (__nv_bfloat16*)(sm + STG128 + 18432);
    __nv_bfloat16* Bh = (__nv_bfloat16*)(sm + STG128 + 36864);
    __nv_bfloat16* Bm = (__nv_bfloat16*)(sm + STG128 + 55296);

    // ---- prologue (once per block) ----
    if (t < 64) {
        const float inv = 1.0f / (float)ROWS;
        float mu  = g_sum1[t]*inv;
        float var = g_sq1[t]*inv - mu*mu;
        if (var < 0.f) var = 0.f;
        float s = g1[t] * rsqrtf(var + BN_EPS);
        f[CTL_SC + t] = s;
        f[CTL_SH + t] = bb1[t] - mu*s;
    }
    if (t < 128) {
        f[CTL_BS + t] = b2[t];
        f[M128_PS + t] = 0.f;
        f[M128_PQ + t] = 0.f;
    }
    {
        const uint32_t* wh = (const uint32_t*)g_W2h;
        const uint32_t* wm = (const uint32_t*)g_W2m;
        for (int i = t; i < 4096; i += 256) {
            int n = i >> 5, kk = i & 31;
            *(uint32_t*)&Bh[n*SA + kk*2] = wh[i];
            *(uint32_t*)&Bm[n*SA + kk*2] = wm[i];
        }
    }
    __syncthreads();

    const int mg = w >> 1, ng = w & 1;
    const int m0 = mg*32;
    const int fr = lane >> 2, c2 = (lane & 3)*2;
    const int arow = lane & 15;
    const uint32_t acolB = (uint32_t)(lane >> 4) * 16u;
    const uint32_t aHa = s2u(Ah + (m0 + arow)*SA) + acolB;
    const uint32_t aMa = s2u(Am + (m0 + arow)*SA) + acolB;
    const int brow = ((lane >> 4) << 3) + (lane & 7);
    const uint32_t bcolB = (uint32_t)((lane >> 3) & 1) * 16u;

    // ---- tile loop ----
    for (int ti = blockIdx.x; ti < NTILE; ti += GRID_MID) {
        const long row0 = (long)ti * 128;
        const int group = ti*4 + mg;

        for (int idx = t; idx < 2048; idx += 256) {
            int r = idx >> 4, c4 = idx & 15;
            float4 v = *(const float4*)(g_H1 + (size_t)(row0 + r)*64 + c4*4);
            int c = c4*4;
            float v0 = fmaxf(v.x*f[CTL_SC+c+0] + f[CTL_SH+c+0], 0.f);
            float v1 = fmaxf(v.y*f[CTL_SC+c+1] + f[CTL_SH+c+1], 0.f);
            float v2 = fmaxf(v.z*f[CTL_SC+c+2] + f[CTL_SH+c+2], 0.f);
            float v3 = fmaxf(v.w*f[CTL_SC+c+3] + f[CTL_SH+c+3], 0.f);
            *(unsigned long long*)&Ah[r*SA + c] = pk4(v0, v1, v2, v3);
            *(unsigned long long*)&Am[r*SA + c] =
                pk4(bf16_res(v0), bf16_res(v1), bf16_res(v2), bf16_res(v3));
        }
        __syncthreads();

#pragma unroll 1
        for (int nc = 0; nc < 2; nc++) {
            const int nb = ng*64 + nc*32;
            uint32_t bHa[2], bMa[2];
#pragma unroll
            for (int pg = 0; pg < 2; pg++) {
                bHa[pg] = s2u(Bh + (nb + pg*16 + brow)*SA) + bcolB;
                bMa[pg] = s2u(Bm + (nb + pg*16 + brow)*SA) + bcolB;
            }
            float acc[2][4][4];
#pragma unroll
            for (int mt = 0; mt < 2; mt++)
#pragma unroll
                for (int nt = 0; nt < 4; nt++)
#pragma unroll
                    for (int q = 0; q < 4; q++) acc[mt][nt][q] = 0.f;

#pragma unroll
            for (int ks = 0; ks < 4; ks++) {
                uint32_t aH0[4], aH1[4], aM0[4], aM1[4];
                ldsm4(aH0, aHa + ks*32);
                ldsm4(aH1, aHa + 2304 + ks*32);
                ldsm4(aM0, aMa + ks*32);
                ldsm4(aM1, aMa + 2304 + ks*32);
#pragma unroll
                for (int pg = 0; pg < 2; pg++) {
                    uint32_t bH[4], bM[4];
                    ldsm4(bH, bHa[pg] + ks*32);
                    ldsm4(bM, bMa[pg] + ks*32);
#pragma unroll
                    for (int sub = 0; sub < 2; sub++) {
                        const int nt = 2*pg + sub;
                        mma_bf16(acc[0][nt], aH0, bH[2*sub], bH[2*sub+1]);
                        mma_bf16(acc[0][nt], aH0, bM[2*sub], bM[2*sub+1]);
                        mma_bf16(acc[0][nt], aM0, bH[2*sub], bH[2*sub+1]);
                        mma_bf16(acc[1][nt], aH1, bH[2*sub], bH[2*sub+1]);
                        mma_bf16(acc[1][nt], aH1, bM[2*sub], bM[2*sub+1]);
                        mma_bf16(acc[1][nt], aM1, bH[2*sub], bH[2*sub+1]);
                    }
                }
            }

            // register epilogue for cols nb..nb+31
#pragma unroll
            for (int nt = 0; nt < 4; nt++) {
                const int col = nb + nt*8 + c2;
                const float bA = f[CTL_BS + col], bB = f[CTL_BS + col + 1];
                float v00 = acc[0][nt][0]+bA, v01 = acc[0][nt][1]+bB;
                float v02 = acc[0][nt][2]+bA, v03 = acc[0][nt][3]+bB;
                float v10 = acc[1][nt][0]+bA, v11 = acc[1][nt][1]+bB;
                float v12 = acc[1][nt][2]+bA, v13 = acc[1][nt][3]+bB;
                float s0 = (v00+v02) + (v10+v12);
                float s1 = (v01+v03) + (v11+v13);
                float q0 = (v00*v00+v02*v02) + (v10*v10+v12*v12);
                float q1 = (v01*v01+v03*v03) + (v11*v11+v13*v13);
                float m0v = fmaxf(fmaxf(v00, v02), fmaxf(v10, v12));
                float m1v = fmaxf(fmaxf(v01, v03), fmaxf(v11, v13));
#pragma unroll
                for (int o = 4; o <= 16; o <<= 1) {
                    s0 += __shfl_xor_sync(0xFFFFFFFFu, s0, o);
                    s1 += __shfl_xor_sync(0xFFFFFFFFu, s1, o);
                    q0 += __shfl_xor_sync(0xFFFFFFFFu, q0, o);
                    q1 += __shfl_xor_sync(0xFFFFFFFFu, q1, o);
                    m0v = fmaxf(m0v, __shfl_xor_sync(0xFFFFFFFFu, m0v, o));
                    m1v = fmaxf(m1v, __shfl_xor_sync(0xFFFFFFFFu, m1v, o));
                }
                if (fr == 0) {     // lanes 0..3
                    *(float2*)&g_M2[(size_t)group*128 + col] = make_float2(m0v, m1v);
                    atomicAdd(&f[M128_PS + col],     s0);
                    atomicAdd(&f[M128_PS + col + 1], s1);
                    atomicAdd(&f[M128_PQ + col],     q0);
                    atomicAdd(&f[M128_PQ + col + 1], q1);
                }
            }
        }
        __syncthreads();   // Ah/Am reads done before next stage
    }

    if (t < 128) {
        atomicAdd(&g_sum2[t], f[M128_PS + t]);
        atomicAdd(&g_sq2[t],  f[M128_PQ + t]);
    }
}

// ------------------------ finalize (params2 + bn2+relu) ---------------------
__global__ __launch_bounds__(256) void finalize_kernel(
    float* __restrict__ outp,
    const float* __restrict__ g2, const float* __restrict__ bb2)
{
    __shared__ float sc[128], sh[128];
    const int t = threadIdx.x;
    if (t < 128) {
        const float inv = 1.0f / (float)ROWS;
        float mu  = g_sum2[t]*inv;
        float var = g_sq2[t]*inv - mu*mu;
        if (var < 0.f) var = 0.f;
        float s = g2[t] * rsqrtf(var + BN_EPS);
        sc[t] = s;
        sh[t] = bb2[t] - mu*s;
    }
    __syncthreads();
    const int base = blockIdx.x*2048;
#pragma unroll
    for (int k = 0; k < 8; k++) {
        int idx = base + k*256 + t;
        int c = idx & 127;
        outp[(size_t)BB*SS*3 + idx] = fmaxf(g_M2[idx]*sc[c] + sh[c], 0.f);
    }
}

// ------------------------------ launcher ------------------------------------
extern "C" void kernel_launch(void* const* d_in, const int* in_sizes, int n_in,
                              void* d_out, int out_size)
{
    const float* xyz    = (const float*)d_in[0];
    const float* points = (const float*)d_in[1];
    const float* W0 = (const float*)d_in[2];
    const float* b0 = (const float*)d_in[3];
    const float* g0 = (const float*)d_in[4];
    const float* bb0= (const float*)d_in[5];
    const float* W1 = (const float*)d_in[6];
    const float* b1 = (const float*)d_in[7];
    const float* g1 = (const float*)d_in[8];
    const float* bb1= (const float*)d_in[9];
    const float* W2 = (const float*)d_in[10];
    const float* b2 = (const float*)d_in[11];
    const float* g2 = (const float*)d_in[12];
    const float* bb2= (const float*)d_in[13];
    float* out = (float*)d_out;

    const int smem_fps    = (NN*3 + 64 + 64) * 4;        // 49664
    const int smem_mid64  = STG + 2*18432 + 2*9216;      // 63488
    const int smem_mid128 = STG128 + 4*18432;            // 76032
    cudaFuncSetAttribute((const void*)fps_prep_kernel,
                         cudaFuncAttributeMaxDynamicSharedMemorySize, smem_fps);
    cudaFuncSetAttribute((const void*)mid64_mma_kernel,
                         cudaFuncAttributeMaxDynamicSharedMemorySize, smem_mid64);
    cudaFuncSetAttribute((const void*)mid128_mma_kernel,
                         cudaFuncAttributeMaxDynamicSharedMemorySize, smem_mid128);

    fps_prep_kernel<<<41, 512, smem_fps>>>(xyz, out, W1, W2);       // 1
    ballquery_kernel<<<(BB*SS)/8, 256>>>(xyz, points, out);         // 2
    mid64_mma_kernel<<<GRID_MID, 256, smem_mid64>>>(W0, b0, g0, bb0, b1);  // 3
    mid128_mma_kernel<<<GRID_MID, 256, smem_mid128>>>(g1, bb1, b2); // 4 <- profiled
    finalize_kernel<<<(BB*SS*128)/2048, 256>>>(out, g2, bb2);       // 5
}

// round 17
// speedup vs baseline: 1.0049x; 1.0049x over previous
#include <cuda_runtime.h>
#include <cuda_bf16.h>
#include <cstdint>

// ---------------------------------------------------------------------------
// PointNet Set Abstraction — round 17.
// fps+prep(1) -> ballquery(2, depth-3 pipeline) -> mid64(3, persistent)
// -> mid128(4, persistent + grid-sync fused finalize). 4 launches.
// ---------------------------------------------------------------------------

#define BB    16
#define NN    4096
#define SS    1024
#define NSAMP 32
#define ROWS  (BB*SS*NSAMP)      // 524288
#define BN_EPS 1e-5f
#define NTILE 4096
#define GRID_MID 444             // 3 blocks/SM x 148 SMs (single wave)

// ------------------------- scratch (device globals) ------------------------
__device__ float g_Xt[9*ROWS];              // gathered features [k][row]
__device__ float g_H1[(size_t)ROWS*64];     // pre-BN layer1 output
__device__ float g_M2[BB*SS*128];           // per-group max of pre-BN layer2

__device__ __align__(16) __nv_bfloat16 g_W1h[64*64],  g_W1m[64*64];
__device__ __align__(16) __nv_bfloat16 g_W2h[128*64], g_W2m[128*64];

__device__ float g_XS[54];                  // [0..8]=Σx, [9..53]=Σxxᵀ (upper)
__device__ float g_sum1[64], g_sq1[64];
__device__ float g_sum2[128], g_sq2[128];
__device__ unsigned g_done;                 // mid128 grid-sync counter

// ----------------------------- mma helpers ---------------------------------
__device__ __forceinline__ void mma_bf16(float* acc, const uint32_t* a,
                                         uint32_t b0, uint32_t b1) {
    asm volatile(
        "mma.sync.aligned.m16n8k16.row.col.f32.bf16.bf16.f32 "
        "{%0,%1,%2,%3}, {%4,%5,%6,%7}, {%8,%9}, {%0,%1,%2,%3};"
        : "+f"(acc[0]), "+f"(acc[1]), "+f"(acc[2]), "+f"(acc[3])
        : "r"(a[0]), "r"(a[1]), "r"(a[2]), "r"(a[3]), "r"(b0), "r"(b1));
}
__device__ __forceinline__ uint32_t pk2(float lo, float hi) {
    uint32_t r;
    asm("cvt.rn.bf16x2.f32 %0, %1, %2;" : "=r"(r) : "f"(hi), "f"(lo));
    return r;
}
__device__ __forceinline__ unsigned long long pk4(float v0, float v1,
                                                  float v2, float v3) {
    unsigned long long r;
    uint32_t lo = pk2(v0, v1), hi = pk2(v2, v3);
    asm("mov.b64 %0, {%1, %2};" : "=l"(r) : "r"(lo), "r"(hi));
    return r;
}
__device__ __forceinline__ float bf16_res(float v) {
    return v - __bfloat162float(__float2bfloat16(v));
}
__device__ __forceinline__ uint32_t s2u(const void* p) {
    return (uint32_t)__cvta_generic_to_shared(p);
}
__device__ __forceinline__ void ldsm4(uint32_t* r, uint32_t a) {
    asm volatile("ldmatrix.sync.aligned.m8n8.x4.shared.b16 {%0,%1,%2,%3}, [%4];"
        : "=r"(r[0]), "=r"(r[1]), "=r"(r[2]), "=r"(r[3]) : "r"(a));
}

// --------------------------- f32x2 helpers ----------------------------------
__device__ __forceinline__ unsigned long long pack2(float lo, float hi) {
    unsigned long long r; asm("mov.b64 %0, {%1, %2};" : "=l"(r) : "f"(lo), "f"(hi)); return r;
}
__device__ __forceinline__ unsigned long long splat2(float x) {
    unsigned long long r; asm("mov.b64 %0, {%1, %1};" : "=l"(r) : "f"(x)); return r;
}
__device__ __forceinline__ float2 unpack2(unsigned long long v) {
    float lo, hi; asm("mov.b64 {%0, %1}, %2;" : "=f"(lo), "=f"(hi) : "l"(v));
    return make_float2(lo, hi);
}
__device__ __forceinline__ unsigned long long add2(unsigned long long a, unsigned long long b) {
    unsigned long long r; asm("add.rn.f32x2 %0, %1, %2;" : "=l"(r) : "l"(a), "l"(b)); return r;
}
__device__ __forceinline__ unsigned long long mul2(unsigned long long a, unsigned long long b) {
    unsigned long long r; asm("mul.rn.f32x2 %0, %1, %2;" : "=l"(r) : "l"(a), "l"(b)); return r;
}
__device__ __forceinline__ unsigned long long fma2p(unsigned long long a, unsigned long long b,
                                                    unsigned long long c) {
    unsigned long long r; asm("fma.rn.f32x2 %0, %1, %2, %3;" : "=l"(r) : "l"(a), "l"(b), "l"(c)); return r;
}

// ------------------------- FPS (blocks 0-15) + prep (16-40) -----------------
__global__ __launch_bounds__(512) void fps_prep_kernel(
    const float* __restrict__ xyz, float* __restrict__ new_xyz,
    const float* __restrict__ W1, const float* __restrict__ W2)
{
    const int bid = blockIdx.x;
    const int t = threadIdx.x;

    if (bid >= 16) {                       // ---- prep roles ----
        if (bid < 24) {
            int i = (bid-16)*512 + t;
            float v = W1[i];
            __nv_bfloat16 h = __float2bfloat16(v);
            g_W1h[i] = h;
            g_W1m[i] = __float2bfloat16(v - __bfloat162float(h));
        } else if (bid < 40) {
            int i = (bid-24)*512 + t;
            float v = W2[i];
            __nv_bfloat16 h = __float2bfloat16(v);
            g_W2h[i] = h;
            g_W2m[i] = __float2bfloat16(v - __bfloat162float(h));
        } else {
            if (t < 54)  g_XS[t] = 0.f;
            if (t < 64)  { g_sum1[t] = 0.f; g_sq1[t] = 0.f; }
            if (t < 128) { g_sum2[t] = 0.f; g_sq2[t] = 0.f; }
            if (t == 128) g_done = 0u;
        }
        return;
    }

    // ---- FPS ----
    extern __shared__ float fsm[];
    float* sxyz = fsm;                     // NN*3
    float* swd  = fsm + NN*3;              // 2*32
    int*   swi  = (int*)(swd + 64);        // 2*32

    const int b = bid;
    const int lane = t & 31, wid = t >> 5;
    const float* Xp = xyz + (long)b*NN*3;

    float lx[8], ly[8], lz[8], dist[8];
#pragma unroll
    for (int i = 0; i < 8; i++) {
        int j = t + i*512;
        float x = Xp[j*3+0], y = Xp[j*3+1], z = Xp[j*3+2];
        lx[i] = x; ly[i] = y; lz[i] = z; dist[i] = 1e10f;
        sxyz[j*3+0] = x; sxyz[j*3+1] = y; sxyz[j*3+2] = z;
    }
    unsigned long long pX[4], pY[4], pZ[4];
#pragma unroll
    for (int j = 0; j < 4; j++) {
        pX[j] = pack2(lx[2*j], lx[2*j+1]);
        pY[j] = pack2(ly[2*j], ly[2*j+1]);
        pZ[j] = pack2(lz[2*j], lz[2*j+1]);
    }
    if (t < 64) { swd[t] = 0.f; swi[t] = 0x7FFFFFFF; }
    __syncthreads();

    int win = 0;
    for (int s = 0; s < SS; s++) {
        const float cx = sxyz[win*3+0], cy = sxyz[win*3+1], cz = sxyz[win*3+2];
        if (t == 0) {
            float* o = new_xyz + ((long)b*SS + s)*3;
            o[0] = cx; o[1] = cy; o[2] = cz;
        }
        const unsigned long long ax = splat2(-cx), ay = splat2(-cy), az = splat2(-cz);
        float bd = -1.0f; int bi = 0;
#pragma unroll
        for (int j = 0; j < 4; j++) {
            unsigned long long dx = add2(pX[j], ax);
            unsigned long long dy = add2(pY[j], ay);
            unsigned long long dz = add2(pZ[j], az);
            unsigned long long dd = mul2(dx, dx);
            dd = fma2p(dy, dy, dd);
            dd = fma2p(dz, dz, dd);
            float2 d = unpack2(dd);
            float dm0 = fminf(dist[2*j],   d.x); dist[2*j]   = dm0;
            if (dm0 > bd) { bd = dm0; bi = t + (2*j)*512; }
            float dm1 = fminf(dist[2*j+1], d.y); dist[2*j+1] = dm1;
            if (dm1 > bd) { bd = dm1; bi = t + (2*j+1)*512; }
        }
        unsigned ud   = __float_as_uint(bd);
        unsigned m    = __reduce_max_sync(0xFFFFFFFFu, ud);
        unsigned cand = (ud == m) ? (unsigned)bi : 0xFFFFFFFFu;
        unsigned wmin = __reduce_min_sync(0xFFFFFFFFu, cand);
        const int p = s & 1;
        if (lane == 0) { swd[p*32+wid] = __uint_as_float(m); swi[p*32+wid] = (int)wmin; }
        __syncthreads();
        float vd = swd[p*32+lane]; int vi = swi[p*32+lane];
        unsigned ud2 = __float_as_uint(vd);
        unsigned m2  = __reduce_max_sync(0xFFFFFFFFu, ud2);
        unsigned c2  = (ud2 == m2) ? (unsigned)vi : 0xFFFFFFFFu;
        win = (int)__reduce_min_sync(0xFFFFFFFFu, c2);
    }
}

// ------------- ball query + gather + xstat (depth-3 pipeline) ---------------
__global__ __launch_bounds__(256) void ballquery_kernel(
    const float* __restrict__ xyz, const float* __restrict__ points,
    const float* __restrict__ new_xyz)
{
    __shared__ int   sidx[8][NSAMP];
    __shared__ float red[8][54];
    const int warp = threadIdx.x >> 5, lane = threadIdx.x & 31;
    const int g = blockIdx.x*8 + warp;
    const int b = g >> 10;
    const float* Xp = xyz + (long)b*NN*3;

    const float cx = new_xyz[g*3+0], cy = new_xyz[g*3+1], cz = new_xyz[g*3+2];
    const float sa = cx*cx + cy*cy + cz*cz;
    const float R2 = (float)(0.2*0.2);
    const unsigned pm = (1u << lane) - 1u;

    int cnt = 0;
    // pipeline registers: cur (c), next (n), next-next (m); 6 floats each
    float cX0 = Xp[lane*3+0],      cY0 = Xp[lane*3+1],      cZ0 = Xp[lane*3+2];
    float cX1 = Xp[(lane+32)*3+0], cY1 = Xp[(lane+32)*3+1], cZ1 = Xp[(lane+32)*3+2];
    float nX0 = Xp[(64+lane)*3+0],    nY0 = Xp[(64+lane)*3+1],    nZ0 = Xp[(64+lane)*3+2];
    float nX1 = Xp[(64+lane+32)*3+0], nY1 = Xp[(64+lane+32)*3+1], nZ1 = Xp[(64+lane+32)*3+2];

    for (int base = 0; base < NN && cnt < NSAMP; base += 64) {
        const int nb2 = (base + 128 < NN) ? base + 128 : base;   // safe prefetch
        float mX0 = Xp[(nb2+lane)*3+0],    mY0 = Xp[(nb2+lane)*3+1],    mZ0 = Xp[(nb2+lane)*3+2];
        float mX1 = Xp[(nb2+lane+32)*3+0], mY1 = Xp[(nb2+lane+32)*3+1], mZ1 = Xp[(nb2+lane+32)*3+2];

        float sb0  = cX0*cX0 + cY0*cY0 + cZ0*cZ0;
        float dot0 = cx*cX0 + cy*cY0 + cz*cZ0;
        float sqr0 = (sa - 2.0f*dot0) + sb0;
        float sb1  = cX1*cX1 + cY1*cY1 + cZ1*cZ1;
        float dot1 = cx*cX1 + cy*cY1 + cz*cZ1;
        float sqr1 = (sa - 2.0f*dot1) + sb1;

        bool v0 = !(sqr0 > R2), v1 = !(sqr1 > R2);
        unsigned m0 = __ballot_sync(0xFFFFFFFFu, v0);
        unsigned m1 = __ballot_sync(0xFFFFFFFFu, v1);
        int pos0 = cnt + __popc(m0 & pm);
        if (v0 && pos0 < NSAMP) sidx[warp][pos0] = base + lane;
        int c0 = cnt + __popc(m0);
        int pos1 = c0 + __popc(m1 & pm);
        if (v1 && pos1 < NSAMP) sidx[warp][pos1] = base + 32 + lane;
        cnt = c0 + __popc(m1);

        cX0 = nX0; cY0 = nY0; cZ0 = nZ0;
        cX1 = nX1; cY1 = nY1; cZ1 = nZ1;
        nX0 = mX0; nY0 = mY0; nZ0 = mZ0;
        nX1 = mX1; nY1 = mY1; nZ1 = mZ1;
    }
    __syncwarp();
    int c = cnt < NSAMP ? cnt : NSAMP;
    int j = sidx[warp][lane < c ? lane : 0];

    const int row = g*NSAMP + lane;
    float xv[9];
    xv[0] = Xp[j*3+0] - cx;
    xv[1] = Xp[j*3+1] - cy;
    xv[2] = Xp[j*3+2] - cz;
    const float* pp = points + ((long)b*NN + j)*6;
#pragma unroll
    for (int q = 0; q < 6; q++) xv[3+q] = pp[q];
#pragma unroll
    for (int k = 0; k < 9; k++) g_Xt[(long)k*ROWS + row] = xv[k];

    float p54[54];
#pragma unroll
    for (int i = 0; i < 9; i++) p54[i] = xv[i];
    {
        int idx = 9;
#pragma unroll
        for (int i = 0; i < 9; i++)
#pragma unroll
            for (int jj = i; jj < 9; jj++) p54[idx++] = xv[i]*xv[jj];
    }
#pragma unroll
    for (int k = 0; k < 54; k++) {
#pragma unroll
        for (int o = 16; o; o >>= 1)
            p54[k] += __shfl_xor_sync(0xFFFFFFFFu, p54[k], o);
    }
    if (lane == 0) {
#pragma unroll
        for (int k = 0; k < 54; k++) red[warp][k] = p54[k];
    }
    __syncthreads();
    if (threadIdx.x < 54) {
        float v = 0.f;
#pragma unroll
        for (int w = 0; w < 8; w++) v += red[w][threadIdx.x];
        atomicAdd(&g_XS[threadIdx.x], v);
    }
}

// --------------------------- smem layouts ------------------------------------
#define CTL_SC   4
#define CTL_SH   68
#define CTL_BS   132
#define CTL_PS   260
#define CTL_PQ   516
#define CTL_W0   772
#define CTL_B0   1348
#define STG      8192
#define M128_PS  260
#define M128_PQ  388
#define STG128   2304
#define SA       72          // padded row stride in bf16 (144 B, 16B-aligned)

// ------------------------------ mid64 (mma) ---------------------------------
// Persistent; 32x32 warp tiles, ldmatrix, tile epilogue; f32x2 A-stage.
__global__ __launch_bounds__(256, 3) void mid64_mma_kernel(
    const float* __restrict__ W0, const float* __restrict__ b0,
    const float* __restrict__ g0, const float* __restrict__ bb0,
    const float* __restrict__ b1)
{
    extern __shared__ __align__(16) char sm[];
    float* f = (float*)sm;
    const int t = threadIdx.x;
    const int w = t >> 5, lane = t & 31;

    __nv_bfloat16* Ah = (__nv_bfloat16*)(sm + STG);
    __nv_bfloat16* Am = (__nv_bfloat16*)(sm + STG + 18432);
    __nv_bfloat16* Bh = (__nv_bfloat16*)(sm + STG + 36864);
    __nv_bfloat16* Bm = (__nv_bfloat16*)(sm + STG + 46080);
    float* tile = (float*)(sm + STG);

    // ---- prologue (once per block) ----
    if (t < 64) {
        float wv[9];
#pragma unroll
        for (int k = 0; k < 9; k++) wv[k] = W0[t*9 + k];
        float sdot = 0.f;
#pragma unroll
        for (int k = 0; k < 9; k++) sdot += wv[k]*g_XS[k];
        float quad = 0.f;
        int idx = 9;
#pragma unroll
        for (int i = 0; i < 9; i++)
#pragma unroll
            for (int jj = i; jj < 9; jj++) {
                float m = g_XS[idx++];
                quad += ((i == jj) ? wv[i]*wv[i] : 2.f*wv[i]*wv[jj]) * m;
            }
        const float N = (float)ROWS;
        float bc  = b0[t];
        float mu  = (sdot + N*bc) / N;
        float Eh2 = (quad + 2.f*bc*sdot + N*bc*bc) / N;
        float var = Eh2 - mu*mu;
        if (var < 0.f) var = 0.f;
        float s = g0[t] * rsqrtf(var + BN_EPS);
        f[CTL_SC + t] = s;
        f[CTL_SH + t] = bb0[t] - mu*s;
        f[CTL_BS + t] = b1[t];
        f[CTL_B0 + t] = b0[t];
    }
    for (int i = t; i < 576; i += 256) {
        int cc = i/9, k = i - cc*9;
        f[CTL_W0 + k*64 + cc] = W0[i];
    }
    {
        const uint32_t* wh = (const uint32_t*)g_W1h;
        const uint32_t* wm = (const uint32_t*)g_W1m;
        for (int i = t; i < 2048; i += 256) {
            int n = i >> 5, kk = i & 31;
            *(uint32_t*)&Bh[n*SA + kk*2] = wh[i];
            *(uint32_t*)&Bm[n*SA + kk*2] = wm[i];
        }
    }
    __syncthreads();

    const int mg = w >> 1, ng = w & 1;
    const int m0 = mg*32, nb = ng*32;
    const int fr = lane >> 2, c2 = (lane & 3)*2;
    const int arow = lane & 15;
    const uint32_t acolB = (uint32_t)(lane >> 4) * 16u;
    const uint32_t aHa = s2u(Ah + (m0 + arow)*SA) + acolB;
    const uint32_t aMa = s2u(Am + (m0 + arow)*SA) + acolB;
    const int brow = ((lane >> 4) << 3) + (lane & 7);
    const uint32_t bcolB = (uint32_t)((lane >> 3) & 1) * 16u;
    uint32_t bHa[2], bMa[2];
#pragma unroll
    for (int pg = 0; pg < 2; pg++) {
        bHa[pg] = s2u(Bh + (nb + pg*16 + brow)*SA) + bcolB;
        bMa[pg] = s2u(Bm + (nb + pg*16 + brow)*SA) + bcolB;
    }
    const int scc = t & 63, sq4 = t >> 6;   // stats role
    float accS = 0.f, accQ = 0.f;

    // ---- tile loop ----
    for (int ti = blockIdx.x; ti < NTILE; ti += GRID_MID) {
        const long row0 = (long)ti * 128;

        // stage A: recompute H0 row r (f32x2); bn0+relu; split (64-bit stores)
        {
            const int r  = t & 127;
            const int cb = (t >> 7) * 32;
            float x[9];
#pragma unroll
            for (int k = 0; k < 9; k++) x[k] = g_Xt[(long)k*ROWS + row0 + r];
            unsigned long long acc2[16];
            {
                const unsigned long long* bp =
                    (const unsigned long long*)(f + CTL_B0 + cb);
#pragma unroll
                for (int c = 0; c < 16; c++) acc2[c] = bp[c];
            }
#pragma unroll
            for (int k = 0; k < 9; k++) {
                unsigned long long xk = splat2(x[k]);
                const unsigned long long* wr =
                    (const unsigned long long*)(f + CTL_W0 + k*64 + cb);
#pragma unroll
                for (int c = 0; c < 16; c++) acc2[c] = fma2p(xk, wr[c], acc2[c]);
            }
            const unsigned long long* scp =
                (const unsigned long long*)(f + CTL_SC + cb);
            const unsigned long long* shp =
                (const unsigned long long*)(f + CTL_SH + cb);
            float av[32];
#pragma unroll
            for (int c = 0; c < 16; c++) {
                unsigned long long r2 = fma2p(acc2[c], scp[c], shp[c]);
                float2 p = unpack2(r2);
                av[2*c]   = fmaxf(p.x, 0.f);
                av[2*c+1] = fmaxf(p.y, 0.f);
            }
#pragma unroll
            for (int j2 = 0; j2 < 8; j2++) {
                float v0 = av[4*j2], v1 = av[4*j2+1];
                float v2 = av[4*j2+2], v3 = av[4*j2+3];
                *(unsigned long long*)&Ah[r*SA + cb + 4*j2] = pk4(v0, v1, v2, v3);
                *(unsigned long long*)&Am[r*SA + cb + 4*j2] =
                    pk4(bf16_res(v0), bf16_res(v1), bf16_res(v2), bf16_res(v3));
            }
        }
        __syncthreads();

        float acc[2][4][4];
#pragma unroll
        for (int mt = 0; mt < 2; mt++)
#pragma unroll
            for (int nt = 0; nt < 4; nt++)
#pragma unroll
                for (int q = 0; q < 4; q++) acc[mt][nt][q] = 0.f;

#pragma unroll
        for (int ks = 0; ks < 4; ks++) {
            uint32_t aH0[4], aH1[4], aM0[4], aM1[4];
            ldsm4(aH0, aHa + ks*32);
            ldsm4(aH1, aHa + 2304 + ks*32);
            ldsm4(aM0, aMa + ks*32);
            ldsm4(aM1, aMa + 2304 + ks*32);
#pragma unroll
            for (int pg = 0; pg < 2; pg++) {
                uint32_t bH[4], bM[4];
                ldsm4(bH, bHa[pg] + ks*32);
                ldsm4(bM, bMa[pg] + ks*32);
#pragma unroll
                for (int sub = 0; sub < 2; sub++) {
                    const int nt = 2*pg + sub;
                    mma_bf16(acc[0][nt], aH0, bH[2*sub], bH[2*sub+1]);
                    mma_bf16(acc[0][nt], aH0, bM[2*sub], bM[2*sub+1]);
                    mma_bf16(acc[0][nt], aM0, bH[2*sub], bH[2*sub+1]);
                    mma_bf16(acc[1][nt], aH1, bH[2*sub], bH[2*sub+1]);
                    mma_bf16(acc[1][nt], aH1, bM[2*sub], bM[2*sub+1]);
                    mma_bf16(acc[1][nt], aM1, bH[2*sub], bH[2*sub+1]);
                }
            }
        }
        __syncthreads();   // A smem done; tile aliases it

#pragma unroll
        for (int mt = 0; mt < 2; mt++)
#pragma unroll
            for (int nt = 0; nt < 4; nt++) {
                const int col = nb + nt*8 + c2;
                float bA = f[CTL_BS + col], bB = f[CTL_BS + col + 1];
                *(float2*)&tile[(m0+mt*16+fr)*68 + col] =
                    make_float2(acc[mt][nt][0]+bA, acc[mt][nt][1]+bB);
                *(float2*)&tile[(m0+mt*16+fr+8)*68 + col] =
                    make_float2(acc[mt][nt][2]+bA, acc[mt][nt][3]+bB);
            }
        __syncthreads();

        {
            float s = 0.f, sq = 0.f;
#pragma unroll
            for (int i = 0; i < 32; i++) {
                float v = tile[(32*sq4 + i)*68 + scc];
                s += v; sq += v*v;
            }
            accS += s; accQ += sq;
        }
        for (int idx = t; idx < 2048; idx += 256) {
            int r = idx >> 4, c4 = idx & 15;
            float4 v = *(const float4*)(tile + r*68 + c4*4);
            *(float4*)(g_H1 + (size_t)(row0 + r)*64 + c4*4) = v;
        }
        __syncthreads();   // tile reads done before next A stage
    }

    // ---- final stats flush ----
    f[CTL_PS + sq4*64 + scc] = accS;
    f[CTL_PQ + sq4*64 + scc] = accQ;
    __syncthreads();
    if (t < 64) {
        float s  = f[CTL_PS+t] + f[CTL_PS+64+t] + f[CTL_PS+128+t] + f[CTL_PS+192+t];
        float sq = f[CTL_PQ+t] + f[CTL_PQ+64+t] + f[CTL_PQ+128+t] + f[CTL_PQ+192+t];
        atomicAdd(&g_sum1[t], s);
        atomicAdd(&g_sq1[t],  sq);
    }
}

// ------------------------------ mid128 (mma) --------------------------------
// Persistent; two 32-col passes, ldmatrix, register epilogue; 64-bit A-staging.
// Grid-sync (all 444 blocks resident) + fused finalize at the end.
__global__ __launch_bounds__(256, 3) void mid128_mma_kernel(
    const float* __restrict__ g1, const float* __restrict__ bb1,
    const float* __restrict__ b2,
    const float* __restrict__ g2, const float* __restrict__ bb2,
    float* __restrict__ outp)
{
    extern __shared__ __align__(16) char sm[];
    float* f = (float*)sm;
    const int t = threadIdx.x;
    const int w = t >> 5, lane = t & 31;

    __nv_bfloat16* Ah = (__nv_bfloat16*)(sm + STG128);
    __nv_bfloat16* Am = (__nv_bfloat16*)(sm + STG128 + 18432);
    __nv_bfloat16* Bh = (__nv_bfloat16*)(sm + STG128 + 36864);
    __nv_bfloat16* Bm = (__nv_bfloat16*)(sm + STG128 + 55296);

    // ---- prologue (once per block) ----
    if (t < 64) {
        const float inv = 1.0f / (float)ROWS;
        float mu  = g_sum1[t]*inv;
        float var = g_sq1[t]*inv - mu*mu;
        if (var < 0.f) var = 0.f;
        float s = g1[t] * rsqrtf(var + BN_EPS);
        f[CTL_SC + t] = s;
        f[CTL_SH + t] = bb1[t] - mu*s;
    }
    if (t < 128) {
        f[CTL_BS + t] = b2[t];
        f[M128_PS + t] = 0.f;
        f[M128_PQ + t] = 0.f;
    }
    {
        const uint32_t* wh = (const uint32_t*)g_W2h;
        const uint32_t* wm = (const uint32_t*)g_W2m;
        for (int i = t; i < 4096; i += 256) {
            int n = i >> 5, kk = i & 31;
            *(uint32_t*)&Bh[n*SA + kk*2] = wh[i];
            *(uint32_t*)&Bm[n*SA + kk*2] = wm[i];
        }
    }
    __syncthreads();

    const int mg = w >> 1, ng = w & 1;
    const int m0 = mg*32;
    const int fr = lane >> 2, c2 = (lane & 3)*2;
    const int arow = lane & 15;
    const uint32_t acolB = (uint32_t)(lane >> 4) * 16u;
    const uint32_t aHa = s2u(Ah + (m0 + arow)*SA) + acolB;
    const uint32_t aMa = s2u(Am + (m0 + arow)*SA) + acolB;
    const int brow = ((lane >> 4) << 3) + (lane & 7);
    const uint32_t bcolB = (uint32_t)((lane >> 3) & 1) * 16u;

    // ---- tile loop ----
    for (int ti = blockIdx.x; ti < NTILE; ti += GRID_MID) {
        const long row0 = (long)ti * 128;
        const int group = ti*4 + mg;

        for (int idx = t; idx < 2048; idx += 256) {
            int r = idx >> 4, c4 = idx & 15;
            float4 v = *(const float4*)(g_H1 + (size_t)(row0 + r)*64 + c4*4);
            int c = c4*4;
            float v0 = fmaxf(v.x*f[CTL_SC+c+0] + f[CTL_SH+c+0], 0.f);
            float v1 = fmaxf(v.y*f[CTL_SC+c+1] + f[CTL_SH+c+1], 0.f);
            float v2 = fmaxf(v.z*f[CTL_SC+c+2] + f[CTL_SH+c+2], 0.f);
            float v3 = fmaxf(v.w*f[CTL_SC+c+3] + f[CTL_SH+c+3], 0.f);
            *(unsigned long long*)&Ah[r*SA + c] = pk4(v0, v1, v2, v3);
            *(unsigned long long*)&Am[r*SA + c] =
                pk4(bf16_res(v0), bf16_res(v1), bf16_res(v2), bf16_res(v3));
        }
        __syncthreads();

#pragma unroll 1
        for (int nc = 0; nc < 2; nc++) {
            const int nb = ng*64 + nc*32;
            uint32_t bHa[2], bMa[2];
#pragma unroll
            for (int pg = 0; pg < 2; pg++) {
                bHa[pg] = s2u(Bh + (nb + pg*16 + brow)*SA) + bcolB;
                bMa[pg] = s2u(Bm + (nb + pg*16 + brow)*SA) + bcolB;
            }
            float acc[2][4][4];
#pragma unroll
            for (int mt = 0; mt < 2; mt++)
#pragma unroll
                for (int nt = 0; nt < 4; nt++)
#pragma unroll
                    for (int q = 0; q < 4; q++) acc[mt][nt][q] = 0.f;

#pragma unroll
            for (int ks = 0; ks < 4; ks++) {
                uint32_t aH0[4], aH1[4], aM0[4], aM1[4];
                ldsm4(aH0, aHa + ks*32);
                ldsm4(aH1, aHa + 2304 + ks*32);
                ldsm4(aM0, aMa + ks*32);
                ldsm4(aM1, aMa + 2304 + ks*32);
#pragma unroll
                for (int pg = 0; pg < 2; pg++) {
                    uint32_t bH[4], bM[4];
                    ldsm4(bH, bHa[pg] + ks*32);
                    ldsm4(bM, bMa[pg] + ks*32);
#pragma unroll
                    for (int sub = 0; sub < 2; sub++) {
                        const int nt = 2*pg + sub;
                        mma_bf16(acc[0][nt], aH0, bH[2*sub], bH[2*sub+1]);
                        mma_bf16(acc[0][nt], aH0, bM[2*sub], bM[2*sub+1]);
                        mma_bf16(acc[0][nt], aM0, bH[2*sub], bH[2*sub+1]);
                        mma_bf16(acc[1][nt], aH1, bH[2*sub], bH[2*sub+1]);
                        mma_bf16(acc[1][nt], aH1, bM[2*sub], bM[2*sub+1]);
                        mma_bf16(acc[1][nt], aM1, bH[2*sub], bH[2*sub+1]);
                    }
                }
            }

            // register epilogue for cols nb..nb+31
#pragma unroll
            for (int nt = 0; nt < 4; nt++) {
                const int col = nb + nt*8 + c2;
                const float bA = f[CTL_BS + col], bB = f[CTL_BS + col + 1];
                float v00 = acc[0][nt][0]+bA, v01 = acc[0][nt][1]+bB;
                float v02 = acc[0][nt][2]+bA, v03 = acc[0][nt][3]+bB;
                float v10 = acc[1][nt][0]+bA, v11 = acc[1][nt][1]+bB;
                float v12 = acc[1][nt][2]+bA, v13 = acc[1][nt][3]+bB;
                float s0 = (v00+v02) + (v10+v12);
                float s1 = (v01+v03) + (v11+v13);
                float q0 = (v00*v00+v02*v02) + (v10*v10+v12*v12);
                float q1 = (v01*v01+v03*v03) + (v11*v11+v13*v13);
                float m0v = fmaxf(fmaxf(v00, v02), fmaxf(v10, v12));
                float m1v = fmaxf(fmaxf(v01, v03), fmaxf(v11, v13));
#pragma unroll
                for (int o = 4; o <= 16; o <<= 1) {
                    s0 += __shfl_xor_sync(0xFFFFFFFFu, s0, o);
                    s1 += __shfl_xor_sync(0xFFFFFFFFu, s1, o);
                    q0 += __shfl_xor_sync(0xFFFFFFFFu, q0, o);
                    q1 += __shfl_xor_sync(0xFFFFFFFFu, q1, o);
                    m0v = fmaxf(m0v, __shfl_xor_sync(0xFFFFFFFFu, m0v, o));
                    m1v = fmaxf(m1v, __shfl_xor_sync(0xFFFFFFFFu, m1v, o));
                }
                if (fr == 0) {     // lanes 0..3
                    *(float2*)&g_M2[(size_t)group*128 + col] = make_float2(m0v, m1v);
                    atomicAdd(&f[M128_PS + col],     s0);
                    atomicAdd(&f[M128_PS + col + 1], s1);
                    atomicAdd(&f[M128_PQ + col],     q0);
                    atomicAdd(&f[M128_PQ + col + 1], q1);
                }
            }
        }
        __syncthreads();   // Ah/Am reads done before next stage
    }

    // ---- stats flush + grid sync + fused finalize ----
    if (t < 128) {
        atomicAdd(&g_sum2[t], f[M128_PS + t]);
        atomicAdd(&g_sq2[t],  f[M128_PQ + t]);
    }
    __threadfence();                    // order M2 stores + stat atomics
    __syncthreads();
    if (t == 0) {
        atomicAdd(&g_done, 1u);
        unsigned v;
        do {
            asm volatile("ld.acquire.gpu.u32 %0, [%1];"
                         : "=r"(v) : "l"(&g_done) : "memory");
            if (v >= (unsigned)GRID_MID) break;
            __nanosleep(200);
        } while (true);
    }
    __syncthreads();

    // params2 (per-block) into smem
    if (t < 128) {
        const float inv = 1.0f / (float)ROWS;
        float mu  = g_sum2[t]*inv;
        float var = g_sq2[t]*inv - mu*mu;
        if (var < 0.f) var = 0.f;
        float s = g2[t] * rsqrtf(var + BN_EPS);
        f[M128_PS + t] = s;                  // sc2
        f[M128_PQ + t] = bb2[t] - mu*s;      // sh2
    }
    __syncthreads();

    // grid-stride finalize over g_M2 -> out
    for (int idx = blockIdx.x*256 + t; idx < BB*SS*128; idx += GRID_MID*256) {
        int c = idx & 127;
        outp[(size_t)BB*SS*3 + idx] =
            fmaxf(g_M2[idx]*f[M128_PS + c] + f[M128_PQ + c], 0.f);
    }
}

// ------------------------------ launcher ------------------------------------
extern "C" void kernel_launch(void* const* d_in, const int* in_sizes, int n_in,
                              void* d_out, int out_size)
{
    const float* xyz    = (const float*)d_in[0];
    const float* points = (const float*)d_in[1];
    const float* W0 = (const float*)d_in[2];
    const float* b0 = (const float*)d_in[3];
    const float* g0 = (const float*)d_in[4];
    const float* bb0= (const float*)d_in[5];
    const float* W1 = (const float*)d_in[6];
    const float* b1 = (const float*)d_in[7];
    const float* g1 = (const float*)d_in[8];
    const float* bb1= (const float*)d_in[9];
    const float* W2 = (const float*)d_in[10];
    const float* b2 = (const float*)d_in[11];
    const float* g2 = (const float*)d_in[12];
    const float* bb2= (const float*)d_in[13];
    float* out = (float*)d_out;

    const int smem_fps    = (NN*3 + 64 + 64) * 4;        // 49664
    const int smem_mid64  = STG + 2*18432 + 2*9216;      // 63488
    const int smem_mid128 = STG128 + 4*18432;            // 76032
    cudaFuncSetAttribute((const void*)fps_prep_kernel,
                         cudaFuncAttributeMaxDynamicSharedMemorySize, smem_fps);
    cudaFuncSetAttribute((const void*)mid64_mma_kernel,
                         cudaFuncAttributeMaxDynamicSharedMemorySize, smem_mid64);
    cudaFuncSetAttribute((const void*)mid128_mma_kernel,
                         cudaFuncAttributeMaxDynamicSharedMemorySize, smem_mid128);

    fps_prep_kernel<<<41, 512, smem_fps>>>(xyz, out, W1, W2);       // 1
    ballquery_kernel<<<(BB*SS)/8, 256>>>(xyz, points, out);         // 2
    mid64_mma_kernel<<<GRID_MID, 256, smem_mid64>>>(W0, b0, g0, bb0, b1);  // 3
    mid128_mma_kernel<<<GRID_MID, 256, smem_mid128>>>(g1, bb1, b2, g2, bb2, out); // 4
}